// round 12
// baseline (speedup 1.0000x reference)
#include <cuda_runtime.h>
#include <cuda_fp16.h>
#include <cstdint>

// ---------------------------------------------------------------------------
// Problem shape
#define NB   32      // batch
#define NT   1000    // time steps
#define NO   1024    // n_out
#define NI   1024    // n_in (K)
#define NTP  1024    // padded T

// Scratch (__device__ globals zero-initialized; pad rows stay zero)
__device__ float g_cur[(size_t)NB * NT * NO];             // currents [b][t][o]
__device__ __half g_xh[(size_t)2 * NB * NTP * NI];        // x fp16 planes [p][b][t][k]
__device__ __half g_wh[(size_t)2 * NO * NI];              // w fp16 planes [p][n][k]

__device__ __forceinline__ uint32_t smem_u32(const void* p) {
    uint32_t a;
    asm("{ .reg .u64 t; cvta.to.shared.u64 t, %1; cvt.u32.u64 %0, t; }" : "=r"(a) : "l"(p));
    return a;
}

// fp32 -> 2x fp16 split (11+11 mantissa bits)
__device__ __forceinline__ void split2_f16(float v, __half& h0, __half& h1) {
    h0 = __float2half_rn(v);
    float r = __fsub_rn(v, __half2float(h0));
    h1 = __float2half_rn(r);
}

// ---------------------------------------------------------------------------
// wconv: w[k][n] (f32) -> g_wh[p][n][k] (fp16 planes, transposed)
// ---------------------------------------------------------------------------
__global__ __launch_bounds__(256)
void wconv_kernel(const float* __restrict__ w)
{
    __shared__ float tile[32][33];
    const int k0 = blockIdx.x * 32;
    const int n0 = blockIdx.y * 32;
    const int tx = threadIdx.x, ty = threadIdx.y;   // (32, 8)
#pragma unroll
    for (int j = 0; j < 4; j++) {
        int k = k0 + ty + 8 * j;
        tile[ty + 8 * j][tx] = w[(size_t)k * NO + n0 + tx];
    }
    __syncthreads();
#pragma unroll
    for (int j = 0; j < 4; j++) {
        int r = ty + 8 * j;
        int n = n0 + r;
        __half h0, h1;
        split2_f16(tile[tx][r], h0, h1);
        size_t base = (size_t)n * NI + k0 + tx;
        g_wh[base]                   = h0;
        g_wh[(size_t)NO * NI + base] = h1;
    }
}

// ---------------------------------------------------------------------------
// xconv: x[b][k][t] (f32) -> g_xh[p][b][t][k] (fp16 planes, transposed per b)
// ---------------------------------------------------------------------------
__global__ __launch_bounds__(256)
void xconv_kernel(const float* __restrict__ x)
{
    __shared__ float tile[32][33];
    const int b  = blockIdx.z;
    const int k0 = blockIdx.y * 32;
    const int t0 = blockIdx.x * 32;
    const int tx = threadIdx.x, ty = threadIdx.y;   // (32, 8)
    const float* xb = x + (size_t)b * NI * NT;
#pragma unroll
    for (int j = 0; j < 4; j++) {
        int k = k0 + ty + 8 * j;
        int t = t0 + tx;
        tile[ty + 8 * j][tx] = (t < NT) ? xb[(size_t)k * NT + t] : 0.0f;
    }
    __syncthreads();
    const size_t plane = (size_t)NB * NTP * NI;
#pragma unroll
    for (int j = 0; j < 4; j++) {
        int r = ty + 8 * j;
        int t = t0 + r;
        if (t < NT) {
            __half h0, h1;
            split2_f16(tile[tx][r], h0, h1);
            size_t base = ((size_t)b * NTP + t) * NI + k0 + tx;
            g_xh[base]         = h0;
            g_xh[plane + base] = h1;
        }
    }
}

// ---------------------------------------------------------------------------
// GEMM via mma.sync.m16n8k16.f16. fp32-emulated fp16x3, accumulation order
// IDENTICAL to the verified R11 kernel (rel_err==0.0):
//   main h0x*h0w -> fresh chunk acc per BK=32, folded to master (rn add);
//   corr h0x*h1w + h1x*h0w chained; final cur = main + corr.
// NEW: k-step fragment software pipeline — ldmatrix for ks+1 issued before
// the mma block of ks, hiding LDS latency behind tensor-pipe time.
// ---------------------------------------------------------------------------
#define PB     16384             // one plane: 128 rows x 64 fp16 (128B rows)
#define BBASE  (2 * PB)          // B planes start within buffer
#define BUFB   (4 * PB)          // [A0][A1][B0][B1] = 64 KB
#define SMEMSZ (2 * BUFB)        // 128 KB
#define NC     16                // 1024 / 64 chunks

__device__ __forceinline__ void ldsm4(uint32_t* r, uint32_t addr) {
    asm volatile("ldmatrix.sync.aligned.m8n8.x4.shared.b16 {%0,%1,%2,%3}, [%4];"
        : "=r"(r[0]), "=r"(r[1]), "=r"(r[2]), "=r"(r[3]) : "r"(addr));
}
__device__ __forceinline__ void mma16816(float* d, const uint32_t* a, uint32_t b0, uint32_t b1) {
    asm volatile("mma.sync.aligned.m16n8k16.row.col.f32.f16.f16.f32 "
        "{%0,%1,%2,%3}, {%4,%5,%6,%7}, {%8,%9}, {%0,%1,%2,%3};"
        : "+f"(d[0]), "+f"(d[1]), "+f"(d[2]), "+f"(d[3])
        : "r"(a[0]), "r"(a[1]), "r"(a[2]), "r"(a[3]), "r"(b0), "r"(b1));
}

__device__ __forceinline__ void load_chunk(uint32_t sbuf,
                                           const __half* xb, const __half* wb,
                                           int k0, int tid,
                                           size_t xplane, size_t wplane)
{
#pragma unroll
    for (int i = 0; i < 16; i++) {
        int v   = tid + i * 256;          // 0..4095
        int sec = v >> 10;                // 0..3
        int row = (v >> 3) & 127;
        int ch  = v & 7;
        const __half* g;
        if (sec < 2) g = xb + (size_t)(sec)     * xplane + (size_t)row * NI + k0 + ch * 8;
        else         g = wb + (size_t)(sec - 2) * wplane + (size_t)row * NI + k0 + ch * 8;
        uint32_t d = sbuf + sec * PB + row * 128 + ((ch ^ (row & 7)) * 16);
        asm volatile("cp.async.cg.shared.global [%0], [%1], 16;" :: "r"(d), "l"((const void*)g));
    }
}

struct Frags {
    uint32_t bf[2][2][4];   // B: plane x n16-group x 4
    uint32_t a0[4][4];      // A h0 plane: mt x 4
    uint32_t a1[4][4];      // A h1 plane: mt x 4
};

__device__ __forceinline__ void load_frags(Frags& f, uint32_t Ab, uint32_t Bb,
                                           int ks, int warp_m, int warp_n,
                                           int rA, int cA, int rB, int cB)
{
#pragma unroll
    for (int p = 0; p < 2; p++)
#pragma unroll
        for (int np = 0; np < 2; np++) {
            int r  = warp_n + np * 16 + rB;
            int ch = (ks * 2 + cB) ^ (r & 7);
            ldsm4(f.bf[p][np], Bb + p * PB + r * 128 + ch * 16);
        }
#pragma unroll
    for (int mt = 0; mt < 4; mt++) {
        int r  = warp_m + mt * 16 + rA;
        int ch = (ks * 2 + cA) ^ (r & 7);
        ldsm4(f.a0[mt], Ab + r * 128 + ch * 16);
        ldsm4(f.a1[mt], Ab + PB + r * 128 + ch * 16);
    }
}

__global__ __launch_bounds__(256, 1)
void snn_gemm_f16()
{
    extern __shared__ char smem[];
    const int tid  = threadIdx.x;
    const int lane = tid & 31;
    const int wid  = tid >> 5;

    const int b  = blockIdx.z;
    const int t0 = blockIdx.y * 128;
    const int n0 = blockIdx.x * 128;

    const size_t xplane = (size_t)NB * NTP * NI;
    const size_t wplane = (size_t)NO * NI;
    const __half* xb = g_xh + ((size_t)b * NTP + t0) * NI;
    const __half* wb = g_wh + (size_t)n0 * NI;

    const uint32_t sb = smem_u32(smem);

    const int warp_m = (wid >> 2) * 64;    // 0 / 64
    const int warp_n = (wid & 3) * 32;     // 0..96

    const int rA = (lane & 7) + ((lane >> 3) & 1) * 8;
    const int cA = (lane >> 4) & 1;
    const int rB = (lane & 7) + ((lane >> 4) & 1) * 8;
    const int cB = (lane >> 3) & 1;

    float accM[4][4][4], accC[4][4][4], accH[4][4][4];
#pragma unroll
    for (int mt = 0; mt < 4; mt++)
#pragma unroll
        for (int nt = 0; nt < 4; nt++)
#pragma unroll
            for (int q = 0; q < 4; q++) { accM[mt][nt][q] = 0.f; accC[mt][nt][q] = 0.f; }

    load_chunk(sb, xb, wb, 0, tid, xplane, wplane);
    asm volatile("cp.async.commit_group;" ::: "memory");

    Frags fr[2];

    for (int c = 0; c < NC; c++) {
        if (c + 1 < NC) {
            load_chunk(sb + ((c + 1) & 1) * BUFB, xb, wb, (c + 1) * 64, tid, xplane, wplane);
            asm volatile("cp.async.commit_group;" ::: "memory");
            asm volatile("cp.async.wait_group 1;" ::: "memory");
        } else {
            asm volatile("cp.async.wait_group 0;" ::: "memory");
        }
        __syncthreads();

        const uint32_t Ab = sb + (c & 1) * BUFB;
        const uint32_t Bb = Ab + BBASE;

        // prime fragment pipeline with ks=0
        load_frags(fr[0], Ab, Bb, 0, warp_m, warp_n, rA, cA, rB, cB);

        // Two BK=32 halves per chunk; fresh chunk accumulator each half
#pragma unroll
        for (int half = 0; half < 2; half++) {
#pragma unroll
            for (int mt = 0; mt < 4; mt++)
#pragma unroll
                for (int nt = 0; nt < 4; nt++)
#pragma unroll
                    for (int q = 0; q < 4; q++) accH[mt][nt][q] = 0.f;

#pragma unroll
            for (int kss = 0; kss < 2; kss++) {
                const int ks = half * 2 + kss;
                Frags& f  = fr[ks & 1];
                // prefetch next ks fragments (overlaps with mma below)
                if (ks < 3)
                    load_frags(fr[(ks + 1) & 1], Ab, Bb, ks + 1,
                               warp_m, warp_n, rA, cA, rB, cB);
#pragma unroll
                for (int mt = 0; mt < 4; mt++) {
#pragma unroll
                    for (int nt = 0; nt < 4; nt++) {
                        // main: h0x * h0w -> chunk accumulator
                        mma16816(accH[mt][nt], f.a0[mt],
                                 f.bf[0][nt >> 1][(nt & 1) * 2], f.bf[0][nt >> 1][(nt & 1) * 2 + 1]);
                        // corr: h0x * h1w
                        mma16816(accC[mt][nt], f.a0[mt],
                                 f.bf[1][nt >> 1][(nt & 1) * 2], f.bf[1][nt >> 1][(nt & 1) * 2 + 1]);
                        // corr: h1x * h0w
                        mma16816(accC[mt][nt], f.a1[mt],
                                 f.bf[0][nt >> 1][(nt & 1) * 2], f.bf[0][nt >> 1][(nt & 1) * 2 + 1]);
                    }
                }
            }

            // fold BK=32 chunk into master (rn add at full magnitude)
#pragma unroll
            for (int mt = 0; mt < 4; mt++)
#pragma unroll
                for (int nt = 0; nt < 4; nt++)
#pragma unroll
                    for (int q = 0; q < 4; q++)
                        accM[mt][nt][q] = __fadd_rn(accM[mt][nt][q], accH[mt][nt][q]);
        }
        __syncthreads();
    }

    // Epilogue: cur = main + corr
    float* __restrict__ cb = g_cur + (size_t)b * NT * NO;
#pragma unroll
    for (int mt = 0; mt < 4; mt++) {
        int r0 = t0 + warp_m + mt * 16 + (lane >> 2);
#pragma unroll
        for (int nt = 0; nt < 4; nt++) {
            int cc = n0 + warp_n + nt * 8 + (lane & 3) * 2;
            float2 v0, v1;
            v0.x = __fadd_rn(accM[mt][nt][0], accC[mt][nt][0]);
            v0.y = __fadd_rn(accM[mt][nt][1], accC[mt][nt][1]);
            v1.x = __fadd_rn(accM[mt][nt][2], accC[mt][nt][2]);
            v1.y = __fadd_rn(accM[mt][nt][3], accC[mt][nt][3]);
            if (r0 < NT)
                *reinterpret_cast<float2*>(cb + (size_t)r0 * NO + cc) = v0;
            if (r0 + 8 < NT)
                *reinterpret_cast<float2*>(cb + (size_t)(r0 + 8) * NO + cc) = v1;
        }
    }
}

// ---------------------------------------------------------------------------
// Scan: per (b,o) neuron, serial over t (exact reference rounding order).
// Streaming loads/stores (read-once / write-once data).
// ---------------------------------------------------------------------------
#define TT 40   // 1000 % 40 == 0

__global__ __launch_bounds__(128)
void snn_scan_kernel(float* __restrict__ out)
{
    __shared__ float s[128][TT + 1];

    const int b  = blockIdx.y;
    const int o0 = blockIdx.x * 128;
    const int o  = o0 + threadIdx.x;

    const float* __restrict__ cb = g_cur + (size_t)b * NT * NO;
    const float DT = (float)(0.001 / 50.0);

    float v = 0.0f;

    for (int tc = 0; tc < NT; tc += TT) {
#pragma unroll
        for (int tt = 0; tt < TT; tt++) {
            float cur;
            asm("ld.global.cs.f32 %0, [%1];" : "=f"(cur)
                : "l"(cb + (size_t)(tc + tt) * NO + o));
            float d  = __fsub_rn(cur, v);
            float dv = __fmul_rn(d, DT);
            v = __fadd_rn(v, dv);
            bool sp = (v >= 1.0f);
            s[threadIdx.x][tt] = sp ? 1.0f : 0.0f;
            v = sp ? 0.0f : v;
        }
        __syncthreads();

        for (int idx = threadIdx.x; idx < 128 * TT; idx += 128) {
            int oo = idx / TT;
            int tt = idx - oo * TT;
            float val = s[oo][tt];
            asm volatile("st.global.cs.f32 [%0], %1;" ::
                "l"(out + ((size_t)b * NO + (o0 + oo)) * NT + tc + tt), "f"(val));
        }
        __syncthreads();
    }
}

// ---------------------------------------------------------------------------
extern "C" void kernel_launch(void* const* d_in, const int* in_sizes, int n_in,
                              void* d_out, int out_size)
{
    const float* x = (const float*)d_in[0];   // [32, 1024, 1000]
    const float* w = (const float*)d_in[1];   // [1024, 1024]
    float* out = (float*)d_out;               // [32, 1024, 1000]

    (void)in_sizes; (void)n_in; (void)out_size;

    cudaFuncSetAttribute(snn_gemm_f16, cudaFuncAttributeMaxDynamicSharedMemorySize, SMEMSZ);

    dim3 wgrid(NI / 32, NO / 32);                 // 32 x 32
    wconv_kernel<<<wgrid, dim3(32, 8)>>>(w);

    dim3 xgrid((NT + 31) / 32, NI / 32, NB);      // 32 x 32 x 32
    xconv_kernel<<<xgrid, dim3(32, 8)>>>(x);

    dim3 ggrid(NO / 128, NTP / 128, NB);          // 8 x 8 x 32
    snn_gemm_f16<<<ggrid, 256, SMEMSZ>>>();

    dim3 sgrid(NO / 128, NB);                     // 8 x 32
    snn_scan_kernel<<<sgrid, 128>>>(out);
}